// round 8
// baseline (speedup 1.0000x reference)
#include <cuda_runtime.h>
#include <cstdint>

namespace {

constexpr int Bsz = 512, Msl = 32, DIN = 1024, DH = 4096, DOUT = 1024;
constexpr int BM = 128, BN = 128, BK = 32;
constexpr int NBUF = 3;
constexpr int A_TILE = BM * BK * 4;       // 16 KB
constexpr int B_TILE = BN * BK * 4;       // 16 KB
constexpr int STAGE  = A_TILE + B_TILE;   // 32 KB
constexpr int SMEM_DYN = NBUF * STAGE;    // 96 KB
constexpr int TPB = 384;                  // 256 consumers + 128 producers

// Intermediate h: [m][b][dh], stored tf32-rounded by layer-1 epilogue.
__device__ float g_h[(size_t)Bsz * Msl * DH];
// x pre-rounded to tf32 bits (pre-pass kernel).
__device__ float g_x_tf[(size_t)Bsz * Msl * DIN];

__device__ __forceinline__ uint32_t f2tf(float f) {
    uint32_t u; asm("cvt.rna.tf32.f32 %0, %1;" : "=r"(u) : "f"(f)); return u;
}
__device__ __forceinline__ uint32_t smem_u32(const void* p) {
    uint32_t a;
    asm("{ .reg .u64 t; cvta.to.shared.u64 t, %1; cvt.u32.u64 %0, t; }" : "=r"(a) : "l"(p));
    return a;
}
__device__ __forceinline__ void cp16(uint32_t dst, const void* src) {
    asm volatile("cp.async.cg.shared.global [%0], [%1], 16;" :: "r"(dst), "l"(src));
}
#define CP_COMMIT() asm volatile("cp.async.commit_group;" ::: "memory")
#define CP_WAIT0()  asm volatile("cp.async.wait_group 0;" ::: "memory")

#define MBAR_INIT(addr, cnt) \
    asm volatile("mbarrier.init.shared.b64 [%0], %1;" :: "r"(addr), "r"(cnt) : "memory")
#define MBAR_ARRIVE(addr) \
    asm volatile("mbarrier.arrive.shared.b64 _, [%0];" :: "r"(addr) : "memory")

__device__ __forceinline__ void mbar_wait(uint32_t mbar, uint32_t parity) {
    uint32_t done;
    asm volatile(
        "{\n\t.reg .pred p;\n\t"
        "mbarrier.try_wait.parity.acquire.cta.shared::cta.b64 p, [%1], %2;\n\t"
        "selp.b32 %0, 1, 0, p;\n\t}"
        : "=r"(done) : "r"(mbar), "r"(parity) : "memory");
    if (!done) {
        asm volatile(
            "{\n\t.reg .pred P1;\n\t"
            "WAIT_LOOP_%=:\n\t"
            "mbarrier.try_wait.parity.acquire.cta.shared::cta.b64 P1, [%0], %1, 0x989680;\n\t"
            "@P1 bra.uni WAIT_DONE_%=;\n\t"
            "bra.uni WAIT_LOOP_%=;\n\t"
            "WAIT_DONE_%=:\n\t}"
            :: "r"(mbar), "r"(parity) : "memory");
    }
}

__device__ __forceinline__ void ldsm4(uint32_t r[4], uint32_t addr) {
    asm volatile("ldmatrix.sync.aligned.m8n8.x4.shared.b16 {%0,%1,%2,%3}, [%4];"
                 : "=r"(r[0]), "=r"(r[1]), "=r"(r[2]), "=r"(r[3]) : "r"(addr));
}
__device__ __forceinline__ void mma_tf32(float acc[4], const uint32_t a[4],
                                         uint32_t b0, uint32_t b1) {
    asm volatile(
        "mma.sync.aligned.m16n8k8.row.col.f32.tf32.tf32.f32 "
        "{%0,%1,%2,%3}, {%4,%5,%6,%7}, {%8,%9}, {%0,%1,%2,%3};\n"
        : "+f"(acc[0]), "+f"(acc[1]), "+f"(acc[2]), "+f"(acc[3])
        : "r"(a[0]), "r"(a[1]), "r"(a[2]), "r"(a[3]), "r"(b0), "r"(b1));
}

// Pre-pass: round x to tf32 bits (vectorized).
__global__ void __launch_bounds__(256)
cvt_tf32(const float4* __restrict__ in, float4* __restrict__ out, int n4) {
    int i = blockIdx.x * blockDim.x + threadIdx.x;
    if (i < n4) {
        float4 v = in[i];
        float4 o;
        o.x = __uint_as_float(f2tf(v.x));
        o.y = __uint_as_float(f2tf(v.y));
        o.z = __uint_as_float(f2tf(v.z));
        o.w = __uint_as_float(f2tf(v.w));
        out[i] = o;
    }
}

// Warp-specialized GEMM: C[BM,BN] tile of A[*,K] x W[K,*] (+bias, ReLU opt),
// batch = blockIdx.z.
// Threads 0..255   : consumers — LDSM + MMA + epilogue only.
// Threads 256..383 : producers — cp.async A (pre-rounded tf32) + LDG/rna/
//                    transpose/STS for B, through a 3-stage mbarrier ring.
template<bool RELU, bool ROUND_OUT>
__global__ void __launch_bounds__(TPB, 1)
gemm_tf32(const float* __restrict__ Ag, const float* __restrict__ Wg,
          const float* __restrict__ biasg, float* __restrict__ Cg,
          int K,
          long aBatch, int lda, long wBatch, int ldw,
          long biasBatch, long cBatch, int ldc)
{
    extern __shared__ char sm[];
    __shared__ __align__(8) uint64_t s_full[NBUF], s_empty[NBUF];
    const uint32_t sb = smem_u32(sm);

    const int tid = threadIdx.x;

    const int m0 = blockIdx.y * BM;
    const int n0 = blockIdx.x * BN;
    const float* A    = Ag    + (size_t)blockIdx.z * aBatch;
    const float* W    = Wg    + (size_t)blockIdx.z * wBatch;
    const float* bias = biasg + (size_t)blockIdx.z * biasBatch;
    float*       C    = Cg    + (size_t)blockIdx.z * cBatch;

    if (tid == 0) {
        #pragma unroll
        for (int i = 0; i < NBUF; ++i) {
            MBAR_INIT(smem_u32(&s_full[i]),  128);   // producer threads
            MBAR_INIT(smem_u32(&s_empty[i]), 256);   // consumer threads
        }
    }
    __syncthreads();

    const int S = K / BK;

    if (tid >= 256) {
        // ================= PRODUCERS (128 threads) =================
        const int ptid = tid - 256;
        const int lane = ptid & 31;
        // A cp.async: 128 rows x 8 groups = 1024 cp16, 8 per thread
        const int a_kg = ptid & 7;
        const int a_r0 = ptid >> 3;              // 0..15, +16 per it
        // B: two 4x4 blocks per thread (k halves), round-5 proven mapping
        const int b_n  = (ptid & 31) * 4;
        const int b_kq = ((ptid >> 5) & 3) * 4;  // 0,4,8,12 (+16 for blk 1)
        const int rot  = (lane >> 1) & 3;

        int ph_e[NBUF];
        #pragma unroll
        for (int i = 0; i < NBUF; ++i) ph_e[i] = 0;

        int buf = 0;
        #pragma unroll 1
        for (int s = 0; s < S; ++s) {
            if (s >= NBUF) { mbar_wait(smem_u32(&s_empty[buf]), ph_e[buf]); ph_e[buf] ^= 1; }

            const int k0 = s * BK;
            const uint32_t base = sb + buf * STAGE;

            // ---- A: global (pre-rounded tf32) -> smem, async ----
            #pragma unroll
            for (int it = 0; it < 8; ++it) {
                const int r = a_r0 + it * 16;
                const uint32_t off = r * 128 + ((a_kg * 16) ^ ((r & 7) << 4));
                cp16(base + off, A + (size_t)(m0 + r) * lda + k0 + a_kg * 4);
            }
            CP_COMMIT();

            // ---- B: LDG + rna + 4x4 transpose + permuted STS ----
            #pragma unroll
            for (int blk = 0; blk < 2; ++blk) {
                const int kl = b_kq + blk * 16;
                const float* wp = W + (size_t)(k0 + kl) * ldw + n0 + b_n;
                float4 r0 = *(const float4*)(wp);
                float4 r1 = *(const float4*)(wp + (size_t)ldw);
                float4 r2 = *(const float4*)(wp + 2 * (size_t)ldw);
                float4 r3 = *(const float4*)(wp + 3 * (size_t)ldw);
                uint4 c[4];
                c[0].x = f2tf(r0.x); c[0].y = f2tf(r1.x); c[0].z = f2tf(r2.x); c[0].w = f2tf(r3.x);
                c[1].x = f2tf(r0.y); c[1].y = f2tf(r1.y); c[1].z = f2tf(r2.y); c[1].w = f2tf(r3.y);
                c[2].x = f2tf(r0.z); c[2].y = f2tf(r1.z); c[2].z = f2tf(r2.z); c[2].w = f2tf(r3.z);
                c[3].x = f2tf(r0.w); c[3].y = f2tf(r1.w); c[3].z = f2tf(r2.w); c[3].w = f2tf(r3.w);
                char* bb = sm + buf * STAGE + A_TILE;
                #pragma unroll
                for (int j = 0; j < 4; ++j) {
                    const int p = (j + rot) & 3;
                    const int row = b_n + p;
                    const uint32_t off = row * 128 + ((kl * 4) ^ ((row & 7) << 4));
                    *(uint4*)(bb + off) = c[p];
                }
            }

            CP_WAIT0();                           // drain this thread's cpA
            MBAR_ARRIVE(smem_u32(&s_full[buf]));  // release stage to consumers

            if (++buf == NBUF) buf = 0;
        }
    } else {
        // ================= CONSUMERS (256 threads) =================
        const int lane = tid & 31, warp = tid >> 5;
        const int g = lane >> 2, tg = lane & 3;
        const int wm = warp & 3, wn = warp >> 2;      // 4 (m) x 2 (n)
        const int lrow = lane & 15;
        const int lkh  = (lane >> 4) << 4;

        float acc[2][8][4];
        #pragma unroll
        for (int i = 0; i < 2; i++)
            #pragma unroll
            for (int j = 0; j < 8; j++)
                #pragma unroll
                for (int q = 0; q < 4; q++) acc[i][j][q] = 0.f;

        int ph_f[NBUF];
        #pragma unroll
        for (int i = 0; i < NBUF; ++i) ph_f[i] = 0;

        int buf = 0;
        #pragma unroll 1
        for (int s = 0; s < S; ++s) {
            mbar_wait(smem_u32(&s_full[buf]), ph_f[buf]); ph_f[buf] ^= 1;

            const uint32_t Ab = sb + buf * STAGE;
            const uint32_t Bb = Ab + A_TILE;
            #pragma unroll
            for (int ks = 0; ks < 4; ++ks) {
                const int kb = ks * 32 + lkh;
                uint32_t af[2][4];
                #pragma unroll
                for (int mt = 0; mt < 2; ++mt) {
                    const int row = wm * 32 + mt * 16 + lrow;
                    ldsm4(af[mt], Ab + row * 128 + (kb ^ ((row & 7) << 4)));
                }
                uint32_t bf[4][4];
                #pragma unroll
                for (int ng = 0; ng < 4; ++ng) {
                    const int row = wn * 64 + ng * 16 + lrow;
                    ldsm4(bf[ng], Bb + row * 128 + (kb ^ ((row & 7) << 4)));
                }
                #pragma unroll
                for (int mt = 0; mt < 2; ++mt)
                    #pragma unroll
                    for (int nt = 0; nt < 8; ++nt)
                        mma_tf32(acc[mt][nt], af[mt],
                                 bf[nt >> 1][nt & 1], bf[nt >> 1][(nt & 1) + 2]);
            }

            MBAR_ARRIVE(smem_u32(&s_empty[buf]));
            if (++buf == NBUF) buf = 0;
        }

        // epilogue: +bias, optional relu, optional tf32 rounding
        #pragma unroll
        for (int mt = 0; mt < 2; ++mt) {
            const int r = m0 + wm * 32 + mt * 16 + g;
            #pragma unroll
            for (int nt = 0; nt < 8; ++nt) {
                const int c = n0 + wn * 64 + nt * 8 + tg * 2;
                const float b0v = bias[c], b1v = bias[c + 1];
                float v0 = acc[mt][nt][0] + b0v;
                float v1 = acc[mt][nt][1] + b1v;
                float v2 = acc[mt][nt][2] + b0v;
                float v3 = acc[mt][nt][3] + b1v;
                if (RELU) {
                    v0 = fmaxf(v0, 0.f); v1 = fmaxf(v1, 0.f);
                    v2 = fmaxf(v2, 0.f); v3 = fmaxf(v3, 0.f);
                }
                if (ROUND_OUT) {
                    v0 = __uint_as_float(f2tf(v0));
                    v1 = __uint_as_float(f2tf(v1));
                    v2 = __uint_as_float(f2tf(v2));
                    v3 = __uint_as_float(f2tf(v3));
                }
                float2 p0; p0.x = v0; p0.y = v1;
                float2 p1; p1.x = v2; p1.y = v3;
                *(float2*)(C + (size_t)r * ldc + c)       = p0;
                *(float2*)(C + (size_t)(r + 8) * ldc + c) = p1;
            }
        }
    }
}

} // anonymous namespace

extern "C" void kernel_launch(void* const* d_in, const int* in_sizes, int n_in,
                              void* d_out, int out_size) {
    (void)in_sizes; (void)n_in; (void)out_size;
    const float* x  = (const float*)d_in[0];  // [B, M, DIN]
    const float* W1 = (const float*)d_in[1];  // [M, DIN, DH]
    const float* b1 = (const float*)d_in[2];  // [M, DH]
    const float* W2 = (const float*)d_in[3];  // [M, DH, DOUT]
    const float* b2 = (const float*)d_in[4];  // [M, DOUT]
    float* out = (float*)d_out;               // [B, M, DOUT]

    float* h = nullptr;
    cudaGetSymbolAddress((void**)&h, g_h);
    float* x_tf = nullptr;
    cudaGetSymbolAddress((void**)&x_tf, g_x_tf);

    cudaFuncSetAttribute(gemm_tf32<true, true>,   cudaFuncAttributeMaxDynamicSharedMemorySize, SMEM_DYN);
    cudaFuncSetAttribute(gemm_tf32<false, false>, cudaFuncAttributeMaxDynamicSharedMemorySize, SMEM_DYN);

    // Pre-pass: x -> tf32 bits (~19 us)
    {
        const int n4 = Bsz * Msl * DIN / 4;
        cvt_tf32<<<(n4 + 255) / 256, 256>>>((const float4*)x, (float4*)x_tf, n4);
    }

    dim3 blk(TPB);

    // Layer 1: per m, h[b, n] = rna(relu(x[b,:] @ W1 + b1))
    dim3 g1(DH / BN, Bsz / BM, Msl);
    gemm_tf32<true, true><<<g1, blk, SMEM_DYN>>>(
        x_tf, W1, b1, h, DIN,
        /*aBatch*/ (long)DIN,        /*lda*/ Msl * DIN,
        /*wBatch*/ (long)DIN * DH,   /*ldw*/ DH,
        /*biasBatch*/ (long)DH,
        /*cBatch*/ (long)Bsz * DH,   /*ldc*/ DH);

    // Layer 2: per m, out[b, n] = h[b,:] @ W2 + b2
    dim3 g2(DOUT / BN, Bsz / BM, Msl);
    gemm_tf32<false, false><<<g2, blk, SMEM_DYN>>>(
        h, W2, b2, out, DH,
        /*aBatch*/ (long)Bsz * DH,   /*lda*/ DH,
        /*wBatch*/ (long)DH * DOUT,  /*ldw*/ DOUT,
        /*biasBatch*/ (long)DOUT,
        /*cBatch*/ (long)DOUT,       /*ldc*/ Msl * DOUT);
}

// round 9
// speedup vs baseline: 1.4535x; 1.4535x over previous
#include <cuda_runtime.h>
#include <cstdint>

namespace {

constexpr int Bsz = 512, Msl = 32, DIN = 1024, DH = 4096, DOUT = 1024;
constexpr int BM = 128, BN = 128, BK = 32;
constexpr int NBUF = 3;
constexpr int A_TILE = BM * BK * 4;       // 16 KB
constexpr int B_TILE = BN * BK * 4;       // 16 KB
constexpr int STAGE  = A_TILE + B_TILE;   // 32 KB
constexpr int SMEM_DYN = NBUF * STAGE;    // 96 KB -> 2 CTAs/SM = 192 KB

// Intermediate h: [m][b][dh], stored tf32-rounded by layer-1 epilogue.
__device__ float g_h[(size_t)Bsz * Msl * DH];
// x pre-rounded to tf32 bits (pre-pass kernel).
__device__ float g_x_tf[(size_t)Bsz * Msl * DIN];

__device__ __forceinline__ uint32_t f2tf(float f) {
    uint32_t u; asm("cvt.rna.tf32.f32 %0, %1;" : "=r"(u) : "f"(f)); return u;
}
__device__ __forceinline__ uint32_t smem_u32(const void* p) {
    uint32_t a;
    asm("{ .reg .u64 t; cvta.to.shared.u64 t, %1; cvt.u32.u64 %0, t; }" : "=r"(a) : "l"(p));
    return a;
}
__device__ __forceinline__ void cp16(uint32_t dst, const void* src) {
    asm volatile("cp.async.cg.shared.global [%0], [%1], 16;" :: "r"(dst), "l"(src));
}
#define CP_COMMIT() asm volatile("cp.async.commit_group;" ::: "memory")
#define CP_WAIT0()  asm volatile("cp.async.wait_group 0;" ::: "memory")
#define CP_WAIT1()  asm volatile("cp.async.wait_group 1;" ::: "memory")

__device__ __forceinline__ void ldsm4(uint32_t r[4], uint32_t addr) {
    asm volatile("ldmatrix.sync.aligned.m8n8.x4.shared.b16 {%0,%1,%2,%3}, [%4];"
                 : "=r"(r[0]), "=r"(r[1]), "=r"(r[2]), "=r"(r[3]) : "r"(addr));
}
__device__ __forceinline__ void mma_tf32(float acc[4], const uint32_t a[4],
                                         uint32_t b0, uint32_t b1) {
    asm volatile(
        "mma.sync.aligned.m16n8k8.row.col.f32.tf32.tf32.f32 "
        "{%0,%1,%2,%3}, {%4,%5,%6,%7}, {%8,%9}, {%0,%1,%2,%3};\n"
        : "+f"(acc[0]), "+f"(acc[1]), "+f"(acc[2]), "+f"(acc[3])
        : "r"(a[0]), "r"(a[1]), "r"(a[2]), "r"(a[3]), "r"(b0), "r"(b1));
}

// Pre-pass: round x to tf32 bits (vectorized).
__global__ void __launch_bounds__(256)
cvt_tf32(const float4* __restrict__ in, float4* __restrict__ out, int n4) {
    int i = blockIdx.x * blockDim.x + threadIdx.x;
    if (i < n4) {
        float4 v = in[i];
        float4 o;
        o.x = __uint_as_float(f2tf(v.x));
        o.y = __uint_as_float(f2tf(v.y));
        o.z = __uint_as_float(f2tf(v.z));
        o.w = __uint_as_float(f2tf(v.w));
        out[i] = o;
    }
}

// C[BM,BN] tile of A[*,K] x W[K,*] (+bias, optional ReLU), batched over blockIdx.z.
// A: pre-rounded tf32 bits, K-contiguous -> cp.async, TWO stages ahead (wait_group 1).
// W: rows n-contiguous -> LDG two stages ahead + rna + 4x4 reg transpose + permuted STS.
// 3-stage smem ring, one __syncthreads per stage.
// ROUND_OUT: store C tf32-rounded (layer-1 h feeding layer-2's A side).
template<bool RELU, bool ROUND_OUT>
__global__ void __launch_bounds__(256, 2)
gemm_tf32(const float* __restrict__ Ag, const float* __restrict__ Wg,
          const float* __restrict__ biasg, float* __restrict__ Cg,
          int K,
          long aBatch, int lda, long wBatch, int ldw,
          long biasBatch, long cBatch, int ldc)
{
    extern __shared__ char sm[];
    const uint32_t sb = smem_u32(sm);

    const int tid  = threadIdx.x;
    const int lane = tid & 31, warp = tid >> 5;
    const int g = lane >> 2, tg = lane & 3;
    const int wm = warp & 3, wn = warp >> 2;          // 4 (m) x 2 (n) warps

    const int m0 = blockIdx.y * BM;
    const int n0 = blockIdx.x * BN;
    const float* A    = Ag    + (size_t)blockIdx.z * aBatch;
    const float* W    = Wg    + (size_t)blockIdx.z * wBatch;
    const float* bias = biasg + (size_t)blockIdx.z * biasBatch;
    float*       C    = Cg    + (size_t)blockIdx.z * cBatch;

    // A cp.async: thread covers 4 rows x 16B
    const int a_kg = tid & 7;
    const int a_r0 = tid >> 3;
    // B LDG (coalesced): 4x4 block, k warp-constant (round-5 proven mapping)
    const int b_n  = (tid & 31) * 4;
    const int b_k0 = (tid >> 5) * 4;
    const int rot  = (lane >> 1) & 3;

    const int lrow = lane & 15;
    const int lkh  = (lane >> 4) << 4;

    float acc[2][8][4];
    #pragma unroll
    for (int i = 0; i < 2; i++)
        #pragma unroll
        for (int j = 0; j < 8; j++)
            #pragma unroll
            for (int q = 0; q < 4; q++) acc[i][j][q] = 0.f;

    float4 rb[4];

    auto cpA = [&](int k0, int buf) {
        const uint32_t base = sb + buf * STAGE;
        #pragma unroll
        for (int it = 0; it < 4; ++it) {
            const int r = a_r0 + it * 32;
            const uint32_t off = r * 128 + ((a_kg * 16) ^ ((r & 7) << 4));
            cp16(base + off, A + (size_t)(m0 + r) * lda + k0 + a_kg * 4);
        }
    };
    auto ldgB = [&](int k0) {
        const float* wp = W + (size_t)(k0 + b_k0) * ldw + n0 + b_n;
        #pragma unroll
        for (int j = 0; j < 4; ++j)
            rb[j] = *(const float4*)(wp + (size_t)j * ldw);
    };
    auto stsB = [&](int buf) {
        const uint32_t base = buf * STAGE + A_TILE;
        uint4 c[4];
        c[0].x = f2tf(rb[0].x); c[0].y = f2tf(rb[1].x); c[0].z = f2tf(rb[2].x); c[0].w = f2tf(rb[3].x);
        c[1].x = f2tf(rb[0].y); c[1].y = f2tf(rb[1].y); c[1].z = f2tf(rb[2].y); c[1].w = f2tf(rb[3].y);
        c[2].x = f2tf(rb[0].z); c[2].y = f2tf(rb[1].z); c[2].z = f2tf(rb[2].z); c[2].w = f2tf(rb[3].z);
        c[3].x = f2tf(rb[0].w); c[3].y = f2tf(rb[1].w); c[3].z = f2tf(rb[2].w); c[3].w = f2tf(rb[3].w);
        #pragma unroll
        for (int j = 0; j < 4; ++j) {
            const int p = (j + rot) & 3;
            const int row = b_n + p;
            const uint32_t off = row * 128 + ((b_k0 * 4) ^ ((row & 7) << 4));
            *(uint4*)(sm + base + off) = c[p];
        }
    };

    auto compute = [&](int buf) {
        const uint32_t Ab = sb + buf * STAGE;
        const uint32_t Bb = Ab + A_TILE;
        #pragma unroll
        for (int ks = 0; ks < 4; ++ks) {
            const int kb = ks * 32 + lkh;
            uint32_t af[2][4];
            #pragma unroll
            for (int mt = 0; mt < 2; ++mt) {
                const int row = wm * 32 + mt * 16 + lrow;
                ldsm4(af[mt], Ab + row * 128 + (kb ^ ((row & 7) << 4)));
            }
            uint32_t bf[4][4];
            #pragma unroll
            for (int ng = 0; ng < 4; ++ng) {
                const int row = wn * 64 + ng * 16 + lrow;
                ldsm4(bf[ng], Bb + row * 128 + (kb ^ ((row & 7) << 4)));
            }
            #pragma unroll
            for (int mt = 0; mt < 2; ++mt)
                #pragma unroll
                for (int nt = 0; nt < 8; ++nt)
                    mma_tf32(acc[mt][nt], af[mt],
                             bf[nt >> 1][nt & 1], bf[nt >> 1][(nt & 1) + 2]);
        }
    };

    const int S = K / BK;

    // Preamble: A stages 0,1 in flight; B stage 0 in smem; B stage 1 in regs.
    cpA(0, 0); CP_COMMIT();
    cpA(BK, 1); CP_COMMIT();
    ldgB(0);
    stsB(0);
    ldgB(BK);
    CP_WAIT1();            // A(0) complete
    __syncthreads();

    #pragma unroll 1
    for (int s = 0; s < S; ++s) {
        const int buf  = s % NBUF;
        const int buf1 = (s + 1) % NBUF;
        const int buf2 = (s + 2) % NBUF;

        compute(buf);

        if (s + 1 < S) stsB(buf1);                 // rb = stage s+1 (loaded last iter)
        if (s + 2 < S) {
            ldgB((s + 2) * BK);                    // 2-stage B lead
            cpA((s + 2) * BK, buf2); CP_COMMIT();  // 2-stage A lead
            CP_WAIT1();                            // A(s+1) complete
        } else if (s + 1 < S) {
            CP_WAIT0();                            // tail: A(S-1) complete
        }
        __syncthreads();
    }

    // epilogue: +bias, optional relu, optional tf32 rounding, float2 stores
    #pragma unroll
    for (int mt = 0; mt < 2; ++mt) {
        const int r = m0 + wm * 32 + mt * 16 + g;
        #pragma unroll
        for (int nt = 0; nt < 8; ++nt) {
            const int c = n0 + wn * 64 + nt * 8 + tg * 2;
            const float b0v = bias[c], b1v = bias[c + 1];
            float v0 = acc[mt][nt][0] + b0v;
            float v1 = acc[mt][nt][1] + b1v;
            float v2 = acc[mt][nt][2] + b0v;
            float v3 = acc[mt][nt][3] + b1v;
            if (RELU) {
                v0 = fmaxf(v0, 0.f); v1 = fmaxf(v1, 0.f);
                v2 = fmaxf(v2, 0.f); v3 = fmaxf(v3, 0.f);
            }
            if (ROUND_OUT) {
                v0 = __uint_as_float(f2tf(v0));
                v1 = __uint_as_float(f2tf(v1));
                v2 = __uint_as_float(f2tf(v2));
                v3 = __uint_as_float(f2tf(v3));
            }
            float2 p0; p0.x = v0; p0.y = v1;
            float2 p1; p1.x = v2; p1.y = v3;
            *(float2*)(C + (size_t)r * ldc + c)       = p0;
            *(float2*)(C + (size_t)(r + 8) * ldc + c) = p1;
        }
    }
}

} // anonymous namespace

extern "C" void kernel_launch(void* const* d_in, const int* in_sizes, int n_in,
                              void* d_out, int out_size) {
    (void)in_sizes; (void)n_in; (void)out_size;
    const float* x  = (const float*)d_in[0];  // [B, M, DIN]
    const float* W1 = (const float*)d_in[1];  // [M, DIN, DH]
    const float* b1 = (const float*)d_in[2];  // [M, DH]
    const float* W2 = (const float*)d_in[3];  // [M, DH, DOUT]
    const float* b2 = (const float*)d_in[4];  // [M, DOUT]
    float* out = (float*)d_out;               // [B, M, DOUT]

    float* h = nullptr;
    cudaGetSymbolAddress((void**)&h, g_h);
    float* x_tf = nullptr;
    cudaGetSymbolAddress((void**)&x_tf, g_x_tf);

    cudaFuncSetAttribute(gemm_tf32<true, true>,   cudaFuncAttributeMaxDynamicSharedMemorySize, SMEM_DYN);
    cudaFuncSetAttribute(gemm_tf32<false, false>, cudaFuncAttributeMaxDynamicSharedMemorySize, SMEM_DYN);

    // Pre-pass: x -> tf32 bits (~19 us)
    {
        const int n4 = Bsz * Msl * DIN / 4;
        cvt_tf32<<<(n4 + 255) / 256, 256>>>((const float4*)x, (float4*)x_tf, n4);
    }

    dim3 blk(256);

    // Layer 1: per m, h[b, n] = rna(relu(x[b,:] @ W1 + b1))
    dim3 g1(DH / BN, Bsz / BM, Msl);
    gemm_tf32<true, true><<<g1, blk, SMEM_DYN>>>(
        x_tf, W1, b1, h, DIN,
        /*aBatch*/ (long)DIN,        /*lda*/ Msl * DIN,
        /*wBatch*/ (long)DIN * DH,   /*ldw*/ DH,
        /*biasBatch*/ (long)DH,
        /*cBatch*/ (long)Bsz * DH,   /*ldc*/ DH);

    // Layer 2: per m, out[b, n] = h[b,:] @ W2 + b2
    dim3 g2(DOUT / BN, Bsz / BM, Msl);
    gemm_tf32<false, false><<<g2, blk, SMEM_DYN>>>(
        h, W2, b2, out, DH,
        /*aBatch*/ (long)Bsz * DH,   /*lda*/ DH,
        /*wBatch*/ (long)DH * DOUT,  /*ldw*/ DOUT,
        /*biasBatch*/ (long)DOUT,
        /*cBatch*/ (long)DOUT,       /*ldc*/ Msl * DOUT);
}